// round 1
// baseline (speedup 1.0000x reference)
#include <cuda_runtime.h>
#include <cuda_bf16.h>
#include <math.h>

#define NN 50000
#define EE 800000
#define GG 256
#define LL 1000
#define HH 4
#define CC 32
#define FDIM 78
#define EDIM 128
#define VOC 26
#define KK 8
#define LOUTD 993
#define HC 128
#define XTF (CC*LOUTD)

// ---------------- scratch (static device memory; no allocation) ----------------
__device__ __align__(128) float g_h[NN*HC];      // transform output (pre-act)
__device__ __align__(128) float g_out[NN*HC];    // GAT layer output (post relu)
__device__ __align__(16)  float g_asrc[NN*4];
__device__ __align__(16)  float g_adst[NN*4];
__device__ int   g_rowptr[NN+1];
__device__ int   g_cursor[NN];
__device__ int   g_csr[EE];
__device__ __align__(128) float g_B[VOC*LL*HC];  // 13.3MB token->xt table
__device__ float g_wsum[VOC*KK*CC];
__device__ float g_cb2[HC];
__device__ __align__(16) float g_pooled[GG*HC];
__device__ float g_xtpre[GG*HC];
__device__ float g_xc[GG*256];
__device__ float g_h1[GG*1024];
__device__ float g_h2[GG*256];

// ---------------- init ----------------
__global__ void k_zero() {
    int i = blockIdx.x*256 + threadIdx.x;
    if (i < NN) g_cursor[i] = 0;
    if (i < GG*HC) { g_pooled[i] = 0.f; g_xtpre[i] = 0.f; }
    if (i < HC) g_cb2[i] = 0.f;
}

// ---------------- CSR build (by dst) ----------------
__global__ void k_hist(const int* __restrict__ dst) {
    int i = blockIdx.x*256 + threadIdx.x;
    if (i < EE) atomicAdd(&g_cursor[dst[i]], 1);
}

__global__ void k_scan() {
    __shared__ int sS[1024];
    int t = threadIdx.x;
    const int CH = 49;                      // 1024*49 >= 50000
    int b0 = t*CH;
    int sum = 0;
    for (int i = 0; i < CH; i++) { int idx = b0+i; if (idx < NN) sum += g_cursor[idx]; }
    sS[t] = sum; __syncthreads();
    for (int off = 1; off < 1024; off <<= 1) {
        int v = (t >= off) ? sS[t-off] : 0;
        __syncthreads();
        sS[t] += v;
        __syncthreads();
    }
    int run = sS[t] - sum;                  // exclusive prefix
    for (int i = 0; i < CH; i++) {
        int idx = b0+i;
        if (idx < NN) {
            int dg = g_cursor[idx];
            g_rowptr[idx] = run;
            g_cursor[idx] = run;
            run += dg;
        }
    }
    if (t == 1023) g_rowptr[NN] = sS[1023];
}

__global__ void k_scatter(const int* __restrict__ src, const int* __restrict__ dst) {
    int i = blockIdx.x*256 + threadIdx.x;
    if (i < EE) {
        int p = atomicAdd(&g_cursor[dst[i]], 1);
        g_csr[p] = src[i];
    }
}

// ---------------- GAT dense transform: g_h = in @ W ----------------
// block: 64 nodes x 128 cols, 256 threads, 8x4 register tile per thread
__global__ void k_transform(const float* __restrict__ in_ptr, int useGOut,
                            const float* __restrict__ W, int Fin) {
    __shared__ float Ws[32*128];
    __shared__ float inS[32*65];
    const float* in = useGOut ? (const float*)g_out : in_ptr;
    int tid = threadIdx.x;
    int n0 = blockIdx.x * 64;
    int cg = tid & 31;   // col group -> cols cg*4..cg*4+3
    int rg = tid >> 5;   // row group -> nodes rg*8..rg*8+7
    float acc[8][4];
#pragma unroll
    for (int r = 0; r < 8; r++)
#pragma unroll
        for (int m = 0; m < 4; m++) acc[r][m] = 0.f;

    for (int f0 = 0; f0 < Fin; f0 += 32) {
        int fk = Fin - f0; if (fk > 32) fk = 32;
        for (int idx = tid; idx < fk*128; idx += 256) Ws[idx] = W[f0*128 + idx];
        int tot = 64*fk;
        for (int idx = tid; idx < tot; idx += 256) {
            int n, f;
            if (fk == 32) { n = idx >> 5; f = idx & 31; }
            else          { n = idx / fk; f = idx - n*fk; }
            int nn = n0 + n;
            inS[f*65 + n] = (nn < NN) ? in[nn*Fin + f0 + f] : 0.f;
        }
        __syncthreads();
#pragma unroll 4
        for (int f = 0; f < fk; f++) {
            float4 wv = *(const float4*)&Ws[f*128 + cg*4];
#pragma unroll
            for (int r = 0; r < 8; r++) {
                float a = inS[f*65 + rg*8 + r];
                acc[r][0] += a*wv.x; acc[r][1] += a*wv.y;
                acc[r][2] += a*wv.z; acc[r][3] += a*wv.w;
            }
        }
        __syncthreads();
    }
#pragma unroll
    for (int r = 0; r < 8; r++) {
        int n = n0 + rg*8 + r;
        if (n < NN) {
            float4 o;
            o.x = acc[r][0]; o.y = acc[r][1]; o.z = acc[r][2]; o.w = acc[r][3];
            *(float4*)&g_h[n*HC + cg*4] = o;
        }
    }
}

// ---------------- per-node attention coefficients ----------------
// warp per node; lane l handles cols 4l..4l+3 (head = l/8)
__global__ void k_attn(const float* __restrict__ asv, const float* __restrict__ adv) {
    int t = blockIdx.x*256 + threadIdx.x;
    int n = t >> 5, lane = t & 31;
    if (n >= NN) return;
    float4 hv = *(const float4*)&g_h[n*HC + 4*lane];
    float4 a  = *(const float4*)&asv[4*lane];
    float4 b  = *(const float4*)&adv[4*lane];
    float ps = hv.x*a.x + hv.y*a.y + hv.z*a.z + hv.w*a.w;
    float pd = hv.x*b.x + hv.y*b.y + hv.z*b.z + hv.w*b.w;
    ps += __shfl_xor_sync(0xffffffffu, ps, 1);
    ps += __shfl_xor_sync(0xffffffffu, ps, 2);
    ps += __shfl_xor_sync(0xffffffffu, ps, 4);
    pd += __shfl_xor_sync(0xffffffffu, pd, 1);
    pd += __shfl_xor_sync(0xffffffffu, pd, 2);
    pd += __shfl_xor_sync(0xffffffffu, pd, 4);
    if ((lane & 7) == 0) {
        g_asrc[n*4 + (lane>>3)] = ps;
        g_adst[n*4 + (lane>>3)] = pd;
    }
}

__device__ __forceinline__ float lrelu02(float v) { return v > 0.f ? v : 0.2f*v; }

// ---------------- softmax + aggregate: warp per dst node ----------------
__global__ void k_aggregate(const float* __restrict__ bias) {
    __shared__ int    sSrc[8][32];
    __shared__ float4 sP[8][32];
    int w = threadIdx.x >> 5, lane = threadIdx.x & 31;
    int d = blockIdx.x*8 + w;
    if (d >= NN) return;
    int r0 = g_rowptr[d], r1 = g_rowptr[d+1];
    int M = r1 - r0 + 1;                      // + self loop
    float4 adst = *(const float4*)&g_adst[d*4];

    // pass 1: per-head max
    float4 m4 = make_float4(-1e30f, -1e30f, -1e30f, -1e30f);
    for (int i = lane; i < M; i += 32) {
        int s = (i == 0) ? d : g_csr[r0 + i - 1];
        float4 a = *(const float4*)&g_asrc[s*4];
        m4.x = fmaxf(m4.x, lrelu02(a.x + adst.x));
        m4.y = fmaxf(m4.y, lrelu02(a.y + adst.y));
        m4.z = fmaxf(m4.z, lrelu02(a.z + adst.z));
        m4.w = fmaxf(m4.w, lrelu02(a.w + adst.w));
    }
#pragma unroll
    for (int off = 16; off > 0; off >>= 1) {
        m4.x = fmaxf(m4.x, __shfl_xor_sync(0xffffffffu, m4.x, off));
        m4.y = fmaxf(m4.y, __shfl_xor_sync(0xffffffffu, m4.y, off));
        m4.z = fmaxf(m4.z, __shfl_xor_sync(0xffffffffu, m4.z, off));
        m4.w = fmaxf(m4.w, __shfl_xor_sync(0xffffffffu, m4.w, off));
    }

    // pass 2: exp + weighted gather, chunked by 32 edges
    float4 dsum = make_float4(0.f, 0.f, 0.f, 0.f);
    float4 acc  = make_float4(0.f, 0.f, 0.f, 0.f);
    int head = lane >> 3;
    for (int cb = 0; cb < M; cb += 32) {
        int i = cb + lane;
        float4 p = make_float4(0.f, 0.f, 0.f, 0.f);
        int s = 0;
        if (i < M) {
            s = (i == 0) ? d : g_csr[r0 + i - 1];
            float4 a = *(const float4*)&g_asrc[s*4];
            p.x = __expf(lrelu02(a.x + adst.x) - m4.x);
            p.y = __expf(lrelu02(a.y + adst.y) - m4.y);
            p.z = __expf(lrelu02(a.z + adst.z) - m4.z);
            p.w = __expf(lrelu02(a.w + adst.w) - m4.w);
            dsum.x += p.x; dsum.y += p.y; dsum.z += p.z; dsum.w += p.w;
        }
        sSrc[w][lane] = s; sP[w][lane] = p;
        __syncwarp();
        int cnt = M - cb; if (cnt > 32) cnt = 32;
        for (int j = 0; j < cnt; j++) {
            int sj = sSrc[w][j];
            float4 pj = sP[w][j];
            float pk = (head == 0) ? pj.x : (head == 1) ? pj.y : (head == 2) ? pj.z : pj.w;
            float4 hv = *(const float4*)&g_h[sj*HC + 4*lane];
            acc.x += pk*hv.x; acc.y += pk*hv.y; acc.z += pk*hv.z; acc.w += pk*hv.w;
        }
        __syncwarp();
    }
#pragma unroll
    for (int off = 16; off > 0; off >>= 1) {
        dsum.x += __shfl_xor_sync(0xffffffffu, dsum.x, off);
        dsum.y += __shfl_xor_sync(0xffffffffu, dsum.y, off);
        dsum.z += __shfl_xor_sync(0xffffffffu, dsum.z, off);
        dsum.w += __shfl_xor_sync(0xffffffffu, dsum.w, off);
    }
    float den = ((head == 0) ? dsum.x : (head == 1) ? dsum.y : (head == 2) ? dsum.z : dsum.w) + 1e-16f;
    float inv = 1.f/den;
    float4 bv = *(const float4*)&bias[4*lane];
    float4 o;
    o.x = acc.x*inv + bv.x; o.x = o.x > 0.f ? o.x : 0.f;
    o.y = acc.y*inv + bv.y; o.y = o.y > 0.f ? o.y : 0.f;
    o.z = acc.z*inv + bv.z; o.z = o.z > 0.f ? o.z : 0.f;
    o.w = acc.w*inv + bv.w; o.w = o.w > 0.f ? o.w : 0.f;
    *(float4*)&g_out[d*HC + 4*lane] = o;
}

// ---------------- pooling ----------------
__global__ void k_pool(const int* __restrict__ batch) {
    int idx = blockIdx.x*256 + threadIdx.x;
    if (idx >= NN*HC) return;
    int n = idx >> 7, c = idx & 127;
    atomicAdd(&g_pooled[batch[n]*HC + c], g_out[idx]);
}

// ---------------- conv path: wsum, cb2, B table, apply ----------------
__global__ void k_wsum(const float* __restrict__ emb, const float* __restrict__ cw) {
    int v = blockIdx.x;
    int t = threadIdx.x;
    if (t >= CC*KK) return;
    int o = t >> 3, k = t & 7;
    float acc = 0.f;
    for (int i = 0; i < EDIM; i++) acc += emb[v*EDIM + i]*cw[(o*EDIM + i)*KK + k];
    g_wsum[(v*KK + k)*CC + o] = acc;
}

__global__ void k_cb2(const float* __restrict__ cb, const float* __restrict__ Wx) {
    int j = threadIdx.x;     // 128
    int r0 = blockIdx.x*128;
    float local = 0.f;
    for (int r = r0; r < r0+128 && r < XTF; r++)
        local += cb[r/LOUTD]*Wx[r*HC + j];
    atomicAdd(&g_cb2[j], local);
}

// block per tau (0..999), 128 threads (j); acc[v] in registers
__global__ void k_bbuild(const float* __restrict__ Wx) {
    __shared__ float ws[VOC*KK*CC];
    int tau = blockIdx.x;
    int j = threadIdx.x;
    for (int idx = j; idx < VOC*KK*CC; idx += 128) ws[idx] = g_wsum[idx];
    __syncthreads();
    float acc[VOC];
#pragma unroll
    for (int v = 0; v < VOC; v++) acc[v] = 0.f;
    int t0 = tau - 7; if (t0 < 0) t0 = 0;
    int t1 = tau;     if (t1 > LOUTD-1) t1 = LOUTD-1;
    for (int t = t0; t <= t1; t++) {
        int k = tau - t;
        const float* wk = &ws[k*CC];
        for (int o = 0; o < CC; o++) {
            float wv = Wx[(o*LOUTD + t)*HC + j];
#pragma unroll
            for (int v = 0; v < VOC; v++) acc[v] += wk[v*KK*CC + o]*wv;
        }
    }
    for (int v = 0; v < VOC; v++) g_B[(v*LL + tau)*HC + j] = acc[v];
}

__global__ void k_applyB(const int* __restrict__ tgt) {
    int g = blockIdx.x, ch = blockIdx.y, j = threadIdx.x;
    float acc = 0.f;
    int t0 = ch*125;
#pragma unroll 5
    for (int tau = t0; tau < t0+125; tau++) {
        int v = __ldg(&tgt[g*LL + tau]);
        acc += g_B[(v*LL + tau)*HC + j];
    }
    atomicAdd(&g_xtpre[g*HC + j], acc);
}

__global__ void k_xtfin(const float* __restrict__ xb) {
    int g = blockIdx.x, j = threadIdx.x;
    float v = g_xtpre[g*HC + j] + xb[j] + g_cb2[j];
    g_xc[g*256 + 128 + j] = v > 0.f ? v : 0.f;
}

// ---------------- small dense layers ----------------
// Asel: 0=g_pooled 1=g_xc 2=g_h1 3=g_h2 ; Csel: 0=g_xc 1=g_h1 2=g_h2 3=doutp
__global__ void k_fc(int Asel, int lda, const float* __restrict__ W,
                     const float* __restrict__ b, int Csel, float* doutp,
                     int ldc, int K, int Nout, int doRelu) {
    __shared__ float sA[1024];
    const float* A = (Asel == 0) ? g_pooled : (Asel == 1) ? g_xc : (Asel == 2) ? g_h1 : g_h2;
    float* C = (Csel == 0) ? g_xc : (Csel == 1) ? g_h1 : (Csel == 2) ? g_h2 : doutp;
    int g = blockIdx.x;
    for (int k = threadIdx.x; k < K; k += 128) sA[k] = A[g*lda + k];
    __syncthreads();
    int n = blockIdx.y*128 + threadIdx.x;
    if (n >= Nout) return;
    float acc = 0.f;
#pragma unroll 4
    for (int k = 0; k < K; k++) acc += sA[k]*W[k*Nout + n];
    acc += b[n];
    if (doRelu && acc < 0.f) acc = 0.f;
    C[g*ldc + n] = acc;
}

// ---------------- host ----------------
extern "C" void kernel_launch(void* const* d_in, const int* in_sizes, int n_in,
                              void* d_out, int out_size) {
    (void)in_sizes; (void)n_in; (void)out_size;
    const float* x       = (const float*)d_in[0];
    const int*   ei      = (const int*)  d_in[1];
    const int*   batch   = (const int*)  d_in[2];
    const int*   target  = (const int*)  d_in[3];
    const float* W1      = (const float*)d_in[4];
    const float* as1     = (const float*)d_in[5];
    const float* ad1     = (const float*)d_in[6];
    const float* b1      = (const float*)d_in[7];
    const float* Ws      = (const float*)d_in[8];
    const float* ass     = (const float*)d_in[9];
    const float* ads     = (const float*)d_in[10];
    const float* bs      = (const float*)d_in[11];
    const float* fcxd_w  = (const float*)d_in[12];
    const float* fcxd_b  = (const float*)d_in[13];
    const float* emb     = (const float*)d_in[14];
    const float* conv_w  = (const float*)d_in[15];
    const float* conv_b  = (const float*)d_in[16];
    const float* fcxt_w  = (const float*)d_in[17];
    const float* fcxt_b  = (const float*)d_in[18];
    const float* fc1_w   = (const float*)d_in[19];
    const float* fc1_b   = (const float*)d_in[20];
    const float* fc2_w   = (const float*)d_in[21];
    const float* fc2_b   = (const float*)d_in[22];
    const float* out_w   = (const float*)d_in[23];
    const float* out_b   = (const float*)d_in[24];
    const int* esrc = ei;
    const int* edst = ei + EE;

    k_zero<<<(NN+255)/256, 256>>>();

    // CSR by dst (graph is static across layers)
    k_hist<<<(EE+255)/256, 256>>>(edst);
    k_scan<<<1, 1024>>>();
    k_scatter<<<(EE+255)/256, 256>>>(esrc, edst);

    // conv-path precompute (independent; serialized on stream)
    k_wsum<<<VOC, 256>>>(emb, conv_w);
    k_cb2<<<(XTF+127)/128, 128>>>(conv_b, fcxt_w);
    k_bbuild<<<LL, 128>>>(fcxt_w);

    // GAT layer 1
    k_transform<<<(NN+63)/64, 256>>>(x, 0, W1, FDIM);
    k_attn<<<(NN*32+255)/256, 256>>>(as1, ad1);
    k_aggregate<<<(NN+7)/8, 256>>>(b1);
    // GAT layers 2..5
    for (int l = 0; l < 4; l++) {
        k_transform<<<(NN+63)/64, 256>>>(nullptr, 1, Ws + l*HC*HC, HC);
        k_attn<<<(NN*32+255)/256, 256>>>(ass + l*HH*CC, ads + l*HH*CC);
        k_aggregate<<<(NN+7)/8, 256>>>(bs + l*HC);
    }

    // pooling + xd
    k_pool<<<(NN*HC+255)/256, 256>>>(batch);
    k_fc<<<dim3(GG,1), 128>>>(0, HC, fcxd_w, fcxd_b, 0, nullptr, 256, HC, HC, 1);

    // xt via B-table gather
    k_applyB<<<dim3(GG,8), 128>>>(target);
    k_xtfin<<<GG, 128>>>(fcxt_b);

    // MLP head
    k_fc<<<dim3(GG,8), 128>>>(1, 256,  fc1_w, fc1_b, 1, nullptr,        1024, 256,  1024, 1);
    k_fc<<<dim3(GG,2), 128>>>(2, 1024, fc2_w, fc2_b, 2, nullptr,        256,  1024, 256,  1);
    k_fc<<<dim3(GG,1), 128>>>(3, 256,  out_w, out_b, 3, (float*)d_out,  1,    256,  1,    0);
}